// round 10
// baseline (speedup 1.0000x reference)
#include <cuda_runtime.h>
#include <cuda_fp16.h>
#include <cstdint>
#include <math.h>

// Problem constants (fixed shapes from setup_inputs)
#define BATCH   4
#define N1      4096
#define N2      16384
#define D1      512
#define D2      256
#define DO      256
#define M1      (BATCH * N1)   // 16384
#define M2      (BATCH * N2)   // 65536

// ---------------------------------------------------------------------------
// Device scratch (allocation-free rule: __device__ globals)
// ---------------------------------------------------------------------------
__device__ float g_feats1[M1 * DO];                         // 16 MB
__device__ __align__(16) __half gA1f[M1 * D1];              // 16 MB
__device__ __align__(16) __half gA2f[M2 * D2];              // 32 MB
__device__ __align__(16) __half gW1f[DO * D1];
__device__ __align__(16) __half gW2f[DO * D2];
__device__ float4 g_knnw[M2];                               // weights (w0,w1,w2,-)
__device__ int4   g_knni[M2];                               // global feats1 row idx

// ---------------------------------------------------------------------------
// Helpers
// ---------------------------------------------------------------------------
__device__ __forceinline__ uint32_t smem_u32(const void* p) {
    uint32_t a;
    asm("{ .reg .u64 t; cvta.to.shared.u64 t, %1; cvt.u32.u64 %0, t; }"
        : "=r"(a) : "l"(p));
    return a;
}

#define SWZ(o) ((o) ^ (((o) >> 3) & 0x70))

#define CP16(dst, src) \
    asm volatile("cp.async.cg.shared.global [%0], [%1], 16;" :: "r"(dst), "l"(src) : "memory")
#define CP_COMMIT() asm volatile("cp.async.commit_group;" ::: "memory")
#define CP_WAIT0()  asm volatile("cp.async.wait_group 0;" ::: "memory")
#define CP_WAIT1()  asm volatile("cp.async.wait_group 1;" ::: "memory")

__device__ __forceinline__ void ldsm4(uint32_t r[4], uint32_t addr) {
    asm volatile("ldmatrix.sync.aligned.m8n8.x4.shared.b16 {%0,%1,%2,%3}, [%4];"
        : "=r"(r[0]), "=r"(r[1]), "=r"(r[2]), "=r"(r[3]) : "r"(addr));
}
__device__ __forceinline__ void mma_f16(float d[4], const uint32_t a[4], const uint32_t b[2]) {
    asm volatile("mma.sync.aligned.m16n8k16.row.col.f32.f16.f16.f32 "
        "{%0,%1,%2,%3}, {%4,%5,%6,%7}, {%8,%9}, {%0,%1,%2,%3};"
        : "+f"(d[0]), "+f"(d[1]), "+f"(d[2]), "+f"(d[3])
        : "r"(a[0]), "r"(a[1]), "r"(a[2]), "r"(a[3]), "r"(b[0]), "r"(b[1]));
}

// ---------------------------------------------------------------------------
// fp32 -> fp16 convert (round-to-nearest)
// ---------------------------------------------------------------------------
__global__ __launch_bounds__(256)
void cvt_half_kernel(const float* __restrict__ x, __half* __restrict__ y, int n4)
{
    int i = blockIdx.x * blockDim.x + threadIdx.x;
    int stride = gridDim.x * blockDim.x;
    for (; i < n4; i += stride) {
        float4 v = ((const float4*)x)[i];
        ((__half2*)y)[2 * i + 0] = __floats2half2_rn(v.x, v.y);
        ((__half2*)y)[2 * i + 1] = __floats2half2_rn(v.z, v.w);
    }
}

// ---------------------------------------------------------------------------
// 3-NN phase 1: per-target weights + global feats1 row indices.
// ---------------------------------------------------------------------------
#define KNN_THREADS 256
#define KNN_SMEM (N1 * 16)

__global__ __launch_bounds__(KNN_THREADS)
void knn_phase1_kernel(const float* __restrict__ xyz2,
                       const float* __restrict__ xyz1)
{
    extern __shared__ float smem[];
    float4* sx = (float4*)smem;

    const int b   = blockIdx.y;
    const int tid = threadIdx.x;
    const int t   = blockIdx.x * KNN_THREADS + tid;

    for (int i = tid; i < N1; i += KNN_THREADS) {
        const float* p = &xyz1[((size_t)b * N1 + i) * 3];
        float x = p[0], y = p[1], z = p[2];
        sx[i] = make_float4(-2.f * x, -2.f * y, -2.f * z, x * x + y * y + z * z);
    }
    __syncthreads();

    const float* tp = &xyz2[((size_t)b * N2 + t) * 3];
    const float txx = tp[0], tyy = tp[1], tzz = tp[2];

    float k0 = 3.4e38f, k1 = 3.4e38f, k2 = 3.4e38f;
    int   i0 = 0, i1 = 0, i2 = 0;

#pragma unroll 4
    for (int s = 0; s < N1; s++) {
        float4 p = sx[s];
        float key = fmaf(p.x, txx, fmaf(p.y, tyy, fmaf(p.z, tzz, p.w)));
        if (key < k2) {
            if (key < k0)      { k2 = k1; i2 = i1; k1 = k0; i1 = i0; k0 = key; i0 = s; }
            else if (key < k1) { k2 = k1; i2 = i1; k1 = key; i1 = s; }
            else               { k2 = key; i2 = s; }
        }
    }

    float tt = txx * txx + tyy * tyy + tzz * tzz;
    float w0 = 1.f / (k0 + tt + 1e-8f);
    float w1 = 1.f / (k1 + tt + 1e-8f);
    float w2 = 1.f / (k2 + tt + 1e-8f);
    float inv = 1.f / (w0 + w1 + w2);

    int g = b * N2 + t;
    g_knnw[g] = make_float4(w0 * inv, w1 * inv, w2 * inv, 0.f);
    g_knni[g] = make_int4(b * N1 + i0, b * N1 + i1, b * N1 + i2, 0);
}

// ---------------------------------------------------------------------------
// fp16 mma.sync GEMM + BN + ReLU, CTA tile 128x256, 512 threads (16 warps 4x4),
// warp tile 32x64. K-chunk 128 = 2 swizzled 64-col panels per stage.
// Stage: A 32KB (2x16KB panels) | B 64KB (2x32KB panels) = 96KB; 2 stages.
// K1: NC=4 chunks; K2: NC=2 (whole-K resident after one prefetch).
// FUSE_INTERP: epilogue adds 3-NN weighted gather from g_feats1.
// ---------------------------------------------------------------------------
#define STAGE 98304u
#define GEMM_DSMEM (2 * 98304 + 1024)

__device__ __forceinline__ void load_chunk(int tid, int bm, int K,
                                           uint32_t base, int c,
                                           const __half* __restrict__ A,
                                           const __half* __restrict__ B)
{
    uint32_t sb = base + (uint32_t)(c & 1) * STAGE;
    int kc = c << 7;    // 128 fp16 per chunk
    // A: 128 rows x 128 fp16 -> 2 panels of (128 rows x 64 fp16, 128B rows)
    for (int i = tid; i < 2048; i += 512) {
        int row = i >> 4, seg = i & 15;
        uint32_t off = (uint32_t)(seg >> 3) * 16384u
                     + SWZ((uint32_t)(row * 128 + (seg & 7) * 16));
        CP16(sb + off, (const char*)(A + (size_t)(bm + row) * K + kc + seg * 8));
    }
    // B: 256 rows x 128 fp16 -> 2 panels of (256 rows x 64 fp16)
    for (int i = tid; i < 4096; i += 512) {
        int row = i >> 4, seg = i & 15;
        uint32_t off = 32768u + (uint32_t)(seg >> 3) * 32768u
                     + SWZ((uint32_t)(row * 128 + (seg & 7) * 16));
        CP16(sb + off, (const char*)(B + (size_t)row * K + kc + seg * 8));
    }
    CP_COMMIT();
}

template<bool FUSE_INTERP>
__global__ __launch_bounds__(512, 1)
void gemm_mma_kernel(const __half* __restrict__ A,
                     const __half* __restrict__ B,
                     const float* __restrict__ bias,
                     const float* __restrict__ gamma,
                     const float* __restrict__ beta,
                     const float* __restrict__ mean,
                     const float* __restrict__ var,
                     float* __restrict__ C, int K)
{
    extern __shared__ char dsm[];
    __shared__ float sScale[DO], sShift[DO], sBias[DO];

    const int tid  = threadIdx.x;
    const int wid  = tid >> 5;
    const int lane = tid & 31;
    const int wm   = wid >> 2;
    const int wn   = wid & 3;
    const int bm   = blockIdx.x * 128;
    const int NC   = K >> 7;
    uint32_t base  = (smem_u32(dsm) + 1023u) & ~1023u;

    if (tid < DO) {
        float sc = gamma[tid] * rsqrtf(var[tid] + 1e-5f);
        sScale[tid] = sc;
        sShift[tid] = beta[tid] - mean[tid] * sc;
        sBias[tid]  = bias[tid];
    }

    float acc[2][8][4];
#pragma unroll
    for (int mi = 0; mi < 2; mi++)
#pragma unroll
        for (int ni = 0; ni < 8; ni++)
#pragma unroll
            for (int e = 0; e < 4; e++) acc[mi][ni][e] = 0.f;

    load_chunk(tid, bm, K, base, 0, A, B);

    const int arow  = wm * 32 + (lane & 15);
    const int acolb = (lane >> 4) * 16;
    const int g     = lane >> 3;
    const int bnrow = (g >> 1) * 8 + (lane & 7);
    const int bkb   = (g & 1) * 16;

    for (int c = 0; c < NC; c++) {
        if (c + 1 < NC) {
            load_chunk(tid, bm, K, base, c + 1, A, B);
            CP_WAIT1();
        } else {
            CP_WAIT0();
        }
        __syncthreads();

        uint32_t sb = base + (uint32_t)(c & 1) * STAGE;

#pragma unroll
        for (int kk = 0; kk < 8; kk++) {
            uint32_t sA = sb + (uint32_t)(kk >> 2) * 16384u;
            uint32_t sB = sb + 32768u + (uint32_t)(kk >> 2) * 32768u;
            int kin = kk & 3;
            uint32_t af[2][4], bf[8][2];
#pragma unroll
            for (int mi = 0; mi < 2; mi++) {
                uint32_t off = SWZ((uint32_t)((arow + mi * 16) * 128 + kin * 32 + acolb));
                ldsm4(af[mi], sA + off);
            }
#pragma unroll
            for (int p = 0; p < 4; p++) {
                uint32_t r[4];
                uint32_t off = SWZ((uint32_t)((wn * 64 + p * 16 + bnrow) * 128 + kin * 32 + bkb));
                ldsm4(r, sB + off);
                bf[2 * p + 0][0] = r[0]; bf[2 * p + 0][1] = r[1];
                bf[2 * p + 1][0] = r[2]; bf[2 * p + 1][1] = r[3];
            }
#pragma unroll
            for (int mi = 0; mi < 2; mi++)
#pragma unroll
                for (int ni = 0; ni < 8; ni++)
                    mma_f16(acc[mi][ni], af[mi], bf[ni]);
        }
        if (c + 1 < NC) __syncthreads();
    }

    // Epilogue: bias + BN + ReLU (+ optional fused 3-NN interp add)
    const int tr = lane >> 2, tq = lane & 3;
#pragma unroll
    for (int mi = 0; mi < 2; mi++) {
#pragma unroll
        for (int half = 0; half < 2; half++) {
            int row = bm + wm * 32 + mi * 16 + tr + half * 8;
            float4 w4; int4 id4;
            const float *f0 = nullptr, *f1 = nullptr, *f2 = nullptr;
            if (FUSE_INTERP) {
                w4  = g_knnw[row];
                id4 = g_knni[row];
                f0 = g_feats1 + (size_t)id4.x * DO;
                f1 = g_feats1 + (size_t)id4.y * DO;
                f2 = g_feats1 + (size_t)id4.z * DO;
            }
            float* outRow = C + (size_t)row * DO;
#pragma unroll
            for (int ni = 0; ni < 8; ni++) {
                int col = wn * 64 + ni * 8 + 2 * tq;
                int e = half * 2;
                float2 v;
                v.x = fmaxf((acc[mi][ni][e + 0] + sBias[col])     * sScale[col]     + sShift[col],     0.f);
                v.y = fmaxf((acc[mi][ni][e + 1] + sBias[col + 1]) * sScale[col + 1] + sShift[col + 1], 0.f);
                if (FUSE_INTERP) {
                    float2 e0 = *(const float2*)(f0 + col);
                    float2 e1 = *(const float2*)(f1 + col);
                    float2 e2 = *(const float2*)(f2 + col);
                    v.x += w4.x * e0.x + w4.y * e1.x + w4.z * e2.x;
                    v.y += w4.x * e0.y + w4.y * e1.y + w4.z * e2.y;
                }
                *(float2*)(outRow + col) = v;
            }
        }
    }
}

// ---------------------------------------------------------------------------
extern "C" void kernel_launch(void* const* d_in, const int* in_sizes, int n_in,
                              void* d_out, int out_size)
{
    const float* xyz1    = (const float*)d_in[0];
    const float* points1 = (const float*)d_in[1];
    const float* xyz2    = (const float*)d_in[2];
    const float* points2 = (const float*)d_in[3];
    const float* W1  = (const float*)d_in[4];
    const float* b1  = (const float*)d_in[5];
    const float* g1  = (const float*)d_in[6];
    const float* be1 = (const float*)d_in[7];
    const float* m1  = (const float*)d_in[8];
    const float* v1  = (const float*)d_in[9];
    const float* W2  = (const float*)d_in[10];
    const float* b2  = (const float*)d_in[11];
    const float* g2  = (const float*)d_in[12];
    const float* be2 = (const float*)d_in[13];
    const float* m2  = (const float*)d_in[14];
    const float* v2  = (const float*)d_in[15];
    float* out = (float*)d_out;

    float* feats1;
    __half *a1f, *a2f, *w1f, *w2f;
    cudaGetSymbolAddress((void**)&feats1, g_feats1);
    cudaGetSymbolAddress((void**)&a1f, gA1f);
    cudaGetSymbolAddress((void**)&a2f, gA2f);
    cudaGetSymbolAddress((void**)&w1f, gW1f);
    cudaGetSymbolAddress((void**)&w2f, gW2f);

    // 3-NN weights/indices (independent of GEMMs)
    cudaFuncSetAttribute(knn_phase1_kernel,
                         cudaFuncAttributeMaxDynamicSharedMemorySize, KNN_SMEM);
    {
        dim3 grid(N2 / KNN_THREADS, BATCH);
        knn_phase1_kernel<<<grid, KNN_THREADS, KNN_SMEM>>>(xyz2, xyz1);
    }

    // fp32 -> fp16 converts
    cvt_half_kernel<<<2048, 256>>>(points1, a1f, M1 * D1 / 4);
    cvt_half_kernel<<<4096, 256>>>(points2, a2f, M2 * D2 / 4);
    cvt_half_kernel<<<128,  256>>>(W1, w1f, DO * D1 / 4);
    cvt_half_kernel<<<64,   256>>>(W2, w2f, DO * D2 / 4);

    cudaFuncSetAttribute(gemm_mma_kernel<false>,
                         cudaFuncAttributeMaxDynamicSharedMemorySize, GEMM_DSMEM);
    cudaFuncSetAttribute(gemm_mma_kernel<true>,
                         cudaFuncAttributeMaxDynamicSharedMemorySize, GEMM_DSMEM);

    // K1: feats1 = relu(bn(points1 @ W1^T + b1))   [16384, 256]
    gemm_mma_kernel<false><<<M1 / 128, 512, GEMM_DSMEM>>>(a1f, w1f,
                                                          b1, g1, be1, m1, v1,
                                                          feats1, D1);
    // K2 (+fused interp): out = relu(bn(points2 @ W2^T + b2)) + interp3(feats1)
    gemm_mma_kernel<true><<<M2 / 128, 512, GEMM_DSMEM>>>(a2f, w2f,
                                                         b2, g2, be2, m2, v2,
                                                         out, D2);
}

// round 11
// speedup vs baseline: 1.0003x; 1.0003x over previous
#include <cuda_runtime.h>
#include <cuda_fp16.h>
#include <cstdint>
#include <math.h>

// Problem constants (fixed shapes from setup_inputs)
#define BATCH   4
#define N1      4096
#define N2      16384
#define D1      512
#define D2      256
#define DO      256
#define M1      (BATCH * N1)   // 16384
#define M2      (BATCH * N2)   // 65536
#define K1_BLOCKS (M1 / 128)   // 128
#define K2_BLOCKS (M2 / 128)   // 512

// ---------------------------------------------------------------------------
// Device scratch (allocation-free rule: __device__ globals)
// ---------------------------------------------------------------------------
__device__ float g_feats1[M1 * DO];                         // 16 MB
__device__ __align__(16) __half gA1f[M1 * D1];              // 16 MB
__device__ __align__(16) __half gA2f[M2 * D2];              // 32 MB
__device__ __align__(16) __half gW1f[DO * D1];
__device__ __align__(16) __half gW2f[DO * D2];
__device__ float4 g_knnw[M2];                               // weights (w0,w1,w2,-)
__device__ int4   g_knni[M2];                               // global feats1 row idx
__device__ int    g_k1done;                                 // K1 CTA completion count

// ---------------------------------------------------------------------------
// Helpers
// ---------------------------------------------------------------------------
__device__ __forceinline__ uint32_t smem_u32(const void* p) {
    uint32_t a;
    asm("{ .reg .u64 t; cvta.to.shared.u64 t, %1; cvt.u32.u64 %0, t; }"
        : "=r"(a) : "l"(p));
    return a;
}

#define SWZ(o) ((o) ^ (((o) >> 3) & 0x70))

#define CP16(dst, src) \
    asm volatile("cp.async.cg.shared.global [%0], [%1], 16;" :: "r"(dst), "l"(src) : "memory")
#define CP_COMMIT() asm volatile("cp.async.commit_group;" ::: "memory")
#define CP_WAIT0()  asm volatile("cp.async.wait_group 0;" ::: "memory")
#define CP_WAIT1()  asm volatile("cp.async.wait_group 1;" ::: "memory")

__device__ __forceinline__ void ldsm4(uint32_t r[4], uint32_t addr) {
    asm volatile("ldmatrix.sync.aligned.m8n8.x4.shared.b16 {%0,%1,%2,%3}, [%4];"
        : "=r"(r[0]), "=r"(r[1]), "=r"(r[2]), "=r"(r[3]) : "r"(addr));
}
__device__ __forceinline__ void mma_f16(float d[4], const uint32_t a[4], const uint32_t b[2]) {
    asm volatile("mma.sync.aligned.m16n8k16.row.col.f32.f16.f16.f32 "
        "{%0,%1,%2,%3}, {%4,%5,%6,%7}, {%8,%9}, {%0,%1,%2,%3};"
        : "+f"(d[0]), "+f"(d[1]), "+f"(d[2]), "+f"(d[3])
        : "r"(a[0]), "r"(a[1]), "r"(a[2]), "r"(a[3]), "r"(b[0]), "r"(b[1]));
}

// ---------------------------------------------------------------------------
// fp32 -> fp16 convert (round-to-nearest)
// ---------------------------------------------------------------------------
__global__ __launch_bounds__(256)
void cvt_half_kernel(const float* __restrict__ x, __half* __restrict__ y, int n4)
{
    int i = blockIdx.x * blockDim.x + threadIdx.x;
    int stride = gridDim.x * blockDim.x;
    for (; i < n4; i += stride) {
        float4 v = ((const float4*)x)[i];
        ((__half2*)y)[2 * i + 0] = __floats2half2_rn(v.x, v.y);
        ((__half2*)y)[2 * i + 1] = __floats2half2_rn(v.z, v.w);
    }
}

// ---------------------------------------------------------------------------
// 3-NN phase 1: per-target weights + global feats1 row indices.
// Also resets the K1-completion counter for this invocation (stream-ordered
// before the fused GEMM launch).
// ---------------------------------------------------------------------------
#define KNN_THREADS 256
#define KNN_SMEM (N1 * 16)

__global__ __launch_bounds__(KNN_THREADS)
void knn_phase1_kernel(const float* __restrict__ xyz2,
                       const float* __restrict__ xyz1)
{
    if (blockIdx.x == 0 && blockIdx.y == 0 && threadIdx.x == 0)
        g_k1done = 0;

    extern __shared__ float smem[];
    float4* sx = (float4*)smem;

    const int b   = blockIdx.y;
    const int tid = threadIdx.x;
    const int t   = blockIdx.x * KNN_THREADS + tid;

    for (int i = tid; i < N1; i += KNN_THREADS) {
        const float* p = &xyz1[((size_t)b * N1 + i) * 3];
        float x = p[0], y = p[1], z = p[2];
        sx[i] = make_float4(-2.f * x, -2.f * y, -2.f * z, x * x + y * y + z * z);
    }
    __syncthreads();

    const float* tp = &xyz2[((size_t)b * N2 + t) * 3];
    const float txx = tp[0], tyy = tp[1], tzz = tp[2];

    float k0 = 3.4e38f, k1 = 3.4e38f, k2 = 3.4e38f;
    int   i0 = 0, i1 = 0, i2 = 0;

#pragma unroll 4
    for (int s = 0; s < N1; s++) {
        float4 p = sx[s];
        float key = fmaf(p.x, txx, fmaf(p.y, tyy, fmaf(p.z, tzz, p.w)));
        if (key < k2) {
            if (key < k0)      { k2 = k1; i2 = i1; k1 = k0; i1 = i0; k0 = key; i0 = s; }
            else if (key < k1) { k2 = k1; i2 = i1; k1 = key; i1 = s; }
            else               { k2 = key; i2 = s; }
        }
    }

    float tt = txx * txx + tyy * tyy + tzz * tzz;
    float w0 = 1.f / (k0 + tt + 1e-8f);
    float w1 = 1.f / (k1 + tt + 1e-8f);
    float w2 = 1.f / (k2 + tt + 1e-8f);
    float inv = 1.f / (w0 + w1 + w2);

    int g = b * N2 + t;
    g_knnw[g] = make_float4(w0 * inv, w1 * inv, w2 * inv, 0.f);
    g_knni[g] = make_int4(b * N1 + i0, b * N1 + i1, b * N1 + i2, 0);
}

// ---------------------------------------------------------------------------
// Fused dual GEMM + BN + ReLU (+ interp for K2 part).
// Blocks [0, 128):   feats1 = relu(bn(A1 @ W1^T))            K=512
// Blocks [128, 640): out    = relu(bn(A2 @ W2^T)) + interp3  K=256
// K2 blocks' mainloop overlaps K1; the interp gather spins on g_k1done==128.
// GEMM internals identical to the proven R9 config:
// CTA 128x256, 512 thr (16 warps 4x4), warp 32x64, K-chunk 64 (SW128),
// double-buffered cp.async, stage A 16KB | B 32KB.
// ---------------------------------------------------------------------------
#define STAGE 49152u
#define GEMM_DSMEM (2 * 49152 + 1024)

__device__ __forceinline__ void load_chunk(int tid, int bm, int K,
                                           uint32_t base, int c,
                                           const __half* __restrict__ A,
                                           const __half* __restrict__ B)
{
    uint32_t sb = base + (uint32_t)(c & 1) * STAGE;
    int kc = c << 6;
    for (int i = tid; i < 1024; i += 512) {
        int row = i >> 3, seg = i & 7;
        uint32_t off = SWZ((uint32_t)(row * 128 + seg * 16));
        CP16(sb + off, (const char*)(A + (size_t)(bm + row) * K + kc + seg * 8));
    }
    for (int i = tid; i < 2048; i += 512) {
        int row = i >> 3, seg = i & 7;
        uint32_t off = SWZ((uint32_t)(row * 128 + seg * 16));
        CP16(sb + 16384u + off, (const char*)(B + (size_t)row * K + kc + seg * 8));
    }
    CP_COMMIT();
}

__global__ __launch_bounds__(512, 1)
void gemm_fused_kernel(const __half* __restrict__ A1,
                       const __half* __restrict__ W1h,
                       const __half* __restrict__ A2,
                       const __half* __restrict__ W2h,
                       const float* __restrict__ b1, const float* __restrict__ g1,
                       const float* __restrict__ be1, const float* __restrict__ m1,
                       const float* __restrict__ v1,
                       const float* __restrict__ b2, const float* __restrict__ g2,
                       const float* __restrict__ be2, const float* __restrict__ m2,
                       const float* __restrict__ v2,
                       float* __restrict__ feats1,
                       float* __restrict__ out)
{
    extern __shared__ char dsm[];
    __shared__ float sScale[DO], sShift[DO], sBias[DO];

    const bool isK1 = (blockIdx.x < K1_BLOCKS);
    const __half* A  = isK1 ? A1 : A2;
    const __half* Bw = isK1 ? W1h : W2h;
    const float* bias  = isK1 ? b1 : b2;
    const float* gamma = isK1 ? g1 : g2;
    const float* beta  = isK1 ? be1 : be2;
    const float* mean  = isK1 ? m1 : m2;
    const float* var   = isK1 ? v1 : v2;
    float* C = isK1 ? feats1 : out;
    const int K  = isK1 ? D1 : D2;
    const int bm = (isK1 ? blockIdx.x : (blockIdx.x - K1_BLOCKS)) * 128;
    const int NC = K >> 6;

    const int tid  = threadIdx.x;
    const int wid  = tid >> 5;
    const int lane = tid & 31;
    const int wm   = wid >> 2;
    const int wn   = wid & 3;
    uint32_t base  = (smem_u32(dsm) + 1023u) & ~1023u;

    if (tid < DO) {
        float sc = gamma[tid] * rsqrtf(var[tid] + 1e-5f);
        sScale[tid] = sc;
        sShift[tid] = beta[tid] - mean[tid] * sc;
        sBias[tid]  = bias[tid];
    }

    float acc[2][8][4];
#pragma unroll
    for (int mi = 0; mi < 2; mi++)
#pragma unroll
        for (int ni = 0; ni < 8; ni++)
#pragma unroll
            for (int e = 0; e < 4; e++) acc[mi][ni][e] = 0.f;

    load_chunk(tid, bm, K, base, 0, A, Bw);

    const int arow  = wm * 32 + (lane & 15);
    const int acolb = (lane >> 4) * 16;
    const int g     = lane >> 3;
    const int bnrow = (g >> 1) * 8 + (lane & 7);
    const int bkb   = (g & 1) * 16;

    for (int c = 0; c < NC; c++) {
        if (c + 1 < NC) {
            load_chunk(tid, bm, K, base, c + 1, A, Bw);
            CP_WAIT1();
        } else {
            CP_WAIT0();
        }
        __syncthreads();

        uint32_t sb = base + (uint32_t)(c & 1) * STAGE;
        uint32_t sA = sb, sB = sb + 16384u;

#pragma unroll
        for (int kk = 0; kk < 4; kk++) {
            uint32_t af[2][4], bf[8][2];
#pragma unroll
            for (int mi = 0; mi < 2; mi++) {
                uint32_t off = SWZ((uint32_t)((arow + mi * 16) * 128 + kk * 32 + acolb));
                ldsm4(af[mi], sA + off);
            }
#pragma unroll
            for (int p = 0; p < 4; p++) {
                uint32_t r[4];
                uint32_t off = SWZ((uint32_t)((wn * 64 + p * 16 + bnrow) * 128 + kk * 32 + bkb));
                ldsm4(r, sB + off);
                bf[2 * p + 0][0] = r[0]; bf[2 * p + 0][1] = r[1];
                bf[2 * p + 1][0] = r[2]; bf[2 * p + 1][1] = r[3];
            }
#pragma unroll
            for (int mi = 0; mi < 2; mi++)
#pragma unroll
                for (int ni = 0; ni < 8; ni++)
                    mma_f16(acc[mi][ni], af[mi], bf[ni]);
        }
        if (c + 1 < NC) __syncthreads();
    }

    const int tr = lane >> 2, tq = lane & 3;

    if (isK1) {
        // K1 epilogue: bias+BN+ReLU, store feats1, then signal completion.
#pragma unroll
        for (int mi = 0; mi < 2; mi++) {
#pragma unroll
            for (int half = 0; half < 2; half++) {
                int row = bm + wm * 32 + mi * 16 + tr + half * 8;
                float* outRow = C + (size_t)row * DO;
#pragma unroll
                for (int ni = 0; ni < 8; ni++) {
                    int col = wn * 64 + ni * 8 + 2 * tq;
                    int e = half * 2;
                    float2 v;
                    v.x = fmaxf((acc[mi][ni][e + 0] + sBias[col])     * sScale[col]     + sShift[col],     0.f);
                    v.y = fmaxf((acc[mi][ni][e + 1] + sBias[col + 1]) * sScale[col + 1] + sShift[col + 1], 0.f);
                    *(float2*)(outRow + col) = v;
                }
            }
        }
        __threadfence();        // make feats1 stores visible device-wide
        __syncthreads();
        if (tid == 0) atomicAdd(&g_k1done, 1);
    } else {
        // K2 epilogue: wait for all K1 CTAs, then fused interp add + store.
        if (tid == 0) {
            while (true) {
                int done;
                asm volatile("ld.global.acquire.gpu.b32 %0, [%1];"
                             : "=r"(done) : "l"(&g_k1done));
                if (done == K1_BLOCKS) break;
                __nanosleep(64);
            }
        }
        __syncthreads();
        __threadfence();        // acquire: order feats1 reads after flag

#pragma unroll
        for (int mi = 0; mi < 2; mi++) {
#pragma unroll
            for (int half = 0; half < 2; half++) {
                int row = bm + wm * 32 + mi * 16 + tr + half * 8;
                float4 w4  = g_knnw[row];
                int4   id4 = g_knni[row];
                const float* f0 = g_feats1 + (size_t)id4.x * DO;
                const float* f1 = g_feats1 + (size_t)id4.y * DO;
                const float* f2 = g_feats1 + (size_t)id4.z * DO;
                float* outRow = C + (size_t)row * DO;
#pragma unroll
                for (int ni = 0; ni < 8; ni++) {
                    int col = wn * 64 + ni * 8 + 2 * tq;
                    int e = half * 2;
                    float2 v;
                    v.x = fmaxf((acc[mi][ni][e + 0] + sBias[col])     * sScale[col]     + sShift[col],     0.f);
                    v.y = fmaxf((acc[mi][ni][e + 1] + sBias[col + 1]) * sScale[col + 1] + sShift[col + 1], 0.f);
                    float2 e0 = *(const float2*)(f0 + col);
                    float2 e1 = *(const float2*)(f1 + col);
                    float2 e2 = *(const float2*)(f2 + col);
                    v.x += w4.x * e0.x + w4.y * e1.x + w4.z * e2.x;
                    v.y += w4.x * e0.y + w4.y * e1.y + w4.z * e2.y;
                    *(float2*)(outRow + col) = v;
                }
            }
        }
    }
}

// ---------------------------------------------------------------------------
extern "C" void kernel_launch(void* const* d_in, const int* in_sizes, int n_in,
                              void* d_out, int out_size)
{
    const float* xyz1    = (const float*)d_in[0];
    const float* points1 = (const float*)d_in[1];
    const float* xyz2    = (const float*)d_in[2];
    const float* points2 = (const float*)d_in[3];
    const float* W1  = (const float*)d_in[4];
    const float* b1  = (const float*)d_in[5];
    const float* g1  = (const float*)d_in[6];
    const float* be1 = (const float*)d_in[7];
    const float* m1  = (const float*)d_in[8];
    const float* v1  = (const float*)d_in[9];
    const float* W2  = (const float*)d_in[10];
    const float* b2  = (const float*)d_in[11];
    const float* g2  = (const float*)d_in[12];
    const float* be2 = (const float*)d_in[13];
    const float* m2  = (const float*)d_in[14];
    const float* v2  = (const float*)d_in[15];
    float* out = (float*)d_out;

    float* feats1;
    __half *a1f, *a2f, *w1f, *w2f;
    cudaGetSymbolAddress((void**)&feats1, g_feats1);
    cudaGetSymbolAddress((void**)&a1f, gA1f);
    cudaGetSymbolAddress((void**)&a2f, gA2f);
    cudaGetSymbolAddress((void**)&w1f, gW1f);
    cudaGetSymbolAddress((void**)&w2f, gW2f);

    // 3-NN weights/indices + counter reset (stream-ordered before GEMM)
    cudaFuncSetAttribute(knn_phase1_kernel,
                         cudaFuncAttributeMaxDynamicSharedMemorySize, KNN_SMEM);
    {
        dim3 grid(N2 / KNN_THREADS, BATCH);
        knn_phase1_kernel<<<grid, KNN_THREADS, KNN_SMEM>>>(xyz2, xyz1);
    }

    // fp32 -> fp16 converts
    cvt_half_kernel<<<2048, 256>>>(points1, a1f, M1 * D1 / 4);
    cvt_half_kernel<<<4096, 256>>>(points2, a2f, M2 * D2 / 4);
    cvt_half_kernel<<<128,  256>>>(W1, w1f, DO * D1 / 4);
    cvt_half_kernel<<<64,   256>>>(W2, w2f, DO * D2 / 4);

    cudaFuncSetAttribute(gemm_fused_kernel,
                         cudaFuncAttributeMaxDynamicSharedMemorySize, GEMM_DSMEM);

    // Fused K1 + K2(+interp): one launch, 640 CTAs (K1 blocks first).
    gemm_fused_kernel<<<K1_BLOCKS + K2_BLOCKS, 512, GEMM_DSMEM>>>(
        a1f, w1f, a2f, w2f,
        b1, g1, be1, m1, v1,
        b2, g2, be2, m2, v2,
        feats1, out);
}

// round 13
// speedup vs baseline: 1.0181x; 1.0178x over previous
#include <cuda_runtime.h>
#include <cuda_fp16.h>
#include <cstdint>
#include <math.h>

// Problem constants (fixed shapes from setup_inputs)
#define BATCH   4
#define N1      4096
#define N2      16384
#define D1      512
#define D2      256
#define DO      256
#define M1      (BATCH * N1)   // 16384
#define M2      (BATCH * N2)   // 65536
#define K1_BLOCKS (M1 / 128)   // 128
#define K2_BLOCKS (M2 / 128)   // 512

// ---------------------------------------------------------------------------
// Device scratch (allocation-free rule: __device__ globals)
// ---------------------------------------------------------------------------
__device__ float g_feats1[M1 * DO];                         // 16 MB
__device__ __align__(16) __half gA1f[M1 * D1];              // 16 MB
__device__ __align__(16) __half gA2f[M2 * D2];              // 32 MB
__device__ __align__(16) __half gW1f[DO * D1];
__device__ __align__(16) __half gW2f[DO * D2];
__device__ float4 g_knnw[M2];                               // weights (w0,w1,w2,-)
__device__ int4   g_knni[M2];                               // global feats1 row idx
__device__ int    g_k1done;                                 // K1 CTA completion count

// ---------------------------------------------------------------------------
// Helpers
// ---------------------------------------------------------------------------
__device__ __forceinline__ uint32_t smem_u32(const void* p) {
    uint32_t a;
    asm("{ .reg .u64 t; cvta.to.shared.u64 t, %1; cvt.u32.u64 %0, t; }"
        : "=r"(a) : "l"(p));
    return a;
}

#define SWZ(o) ((o) ^ (((o) >> 3) & 0x70))

#define CP16(dst, src) \
    asm volatile("cp.async.cg.shared.global [%0], [%1], 16;" :: "r"(dst), "l"(src) : "memory")
#define CP_COMMIT() asm volatile("cp.async.commit_group;" ::: "memory")
#define CP_WAIT0()  asm volatile("cp.async.wait_group 0;" ::: "memory")
#define CP_WAIT1()  asm volatile("cp.async.wait_group 1;" ::: "memory")
#define CP_WAIT2()  asm volatile("cp.async.wait_group 2;" ::: "memory")

__device__ __forceinline__ void ldsm4(uint32_t r[4], uint32_t addr) {
    asm volatile("ldmatrix.sync.aligned.m8n8.x4.shared.b16 {%0,%1,%2,%3}, [%4];"
        : "=r"(r[0]), "=r"(r[1]), "=r"(r[2]), "=r"(r[3]) : "r"(addr));
}
__device__ __forceinline__ void mma_f16(float d[4], const uint32_t a[4], const uint32_t b[2]) {
    asm volatile("mma.sync.aligned.m16n8k16.row.col.f32.f16.f16.f32 "
        "{%0,%1,%2,%3}, {%4,%5,%6,%7}, {%8,%9}, {%0,%1,%2,%3};"
        : "+f"(d[0]), "+f"(d[1]), "+f"(d[2]), "+f"(d[3])
        : "r"(a[0]), "r"(a[1]), "r"(a[2]), "r"(a[3]), "r"(b[0]), "r"(b[1]));
}

// ---------------------------------------------------------------------------
// fp32 -> fp16 converts
// ---------------------------------------------------------------------------
__global__ __launch_bounds__(256)
void cvt_half_kernel(const float* __restrict__ x, __half* __restrict__ y, int n4)
{
    int i = blockIdx.x * blockDim.x + threadIdx.x;
    int stride = gridDim.x * blockDim.x;
    for (; i < n4; i += stride) {
        float4 v = ((const float4*)x)[i];
        ((__half2*)y)[2 * i + 0] = __floats2half2_rn(v.x, v.y);
        ((__half2*)y)[2 * i + 1] = __floats2half2_rn(v.z, v.w);
    }
}

// Convert three concatenated regions in one launch (points1, W1, W2).
#define CVT1_N4 (M1 * D1 / 4)
#define CVTW1_N4 (DO * D1 / 4)
#define CVTW2_N4 (DO * D2 / 4)

__global__ __launch_bounds__(256)
void cvt_rest_kernel(const float* __restrict__ x1, __half* __restrict__ y1,
                     const float* __restrict__ x2, __half* __restrict__ y2,
                     const float* __restrict__ x3, __half* __restrict__ y3)
{
    int i = blockIdx.x * blockDim.x + threadIdx.x;
    int stride = gridDim.x * blockDim.x;
    int total = CVT1_N4 + CVTW1_N4 + CVTW2_N4;
    for (; i < total; i += stride) {
        const float* x; __half* y; int j;
        if (i < CVT1_N4)                { x = x1; y = y1; j = i; }
        else if (i < CVT1_N4 + CVTW1_N4){ x = x2; y = y2; j = i - CVT1_N4; }
        else                            { x = x3; y = y3; j = i - CVT1_N4 - CVTW1_N4; }
        float4 v = ((const float4*)x)[j];
        ((__half2*)y)[2 * j + 0] = __floats2half2_rn(v.x, v.y);
        ((__half2*)y)[2 * j + 1] = __floats2half2_rn(v.z, v.w);
    }
}

// ---------------------------------------------------------------------------
// 3-NN phase 1: per-target weights + global feats1 row indices.
// Also resets the K1-completion counter (stream-ordered before fused GEMM).
// ---------------------------------------------------------------------------
#define KNN_THREADS 256
#define KNN_SMEM (N1 * 16)

__global__ __launch_bounds__(KNN_THREADS)
void knn_phase1_kernel(const float* __restrict__ xyz2,
                       const float* __restrict__ xyz1)
{
    if (blockIdx.x == 0 && blockIdx.y == 0 && threadIdx.x == 0)
        g_k1done = 0;

    extern __shared__ float smem[];
    float4* sx = (float4*)smem;

    const int b   = blockIdx.y;
    const int tid = threadIdx.x;
    const int t   = blockIdx.x * KNN_THREADS + tid;

    for (int i = tid; i < N1; i += KNN_THREADS) {
        const float* p = &xyz1[((size_t)b * N1 + i) * 3];
        float x = p[0], y = p[1], z = p[2];
        sx[i] = make_float4(-2.f * x, -2.f * y, -2.f * z, x * x + y * y + z * z);
    }
    __syncthreads();

    const float* tp = &xyz2[((size_t)b * N2 + t) * 3];
    const float txx = tp[0], tyy = tp[1], tzz = tp[2];

    float k0 = 3.4e38f, k1 = 3.4e38f, k2 = 3.4e38f;
    int   i0 = 0, i1 = 0, i2 = 0;

#pragma unroll 4
    for (int s = 0; s < N1; s++) {
        float4 p = sx[s];
        float key = fmaf(p.x, txx, fmaf(p.y, tyy, fmaf(p.z, tzz, p.w)));
        if (key < k2) {
            if (key < k0)      { k2 = k1; i2 = i1; k1 = k0; i1 = i0; k0 = key; i0 = s; }
            else if (key < k1) { k2 = k1; i2 = i1; k1 = key; i1 = s; }
            else               { k2 = key; i2 = s; }
        }
    }

    float tt = txx * txx + tyy * tyy + tzz * tzz;
    float w0 = 1.f / (k0 + tt + 1e-8f);
    float w1 = 1.f / (k1 + tt + 1e-8f);
    float w2 = 1.f / (k2 + tt + 1e-8f);
    float inv = 1.f / (w0 + w1 + w2);

    int g = b * N2 + t;
    g_knnw[g] = make_float4(w0 * inv, w1 * inv, w2 * inv, 0.f);
    g_knni[g] = make_int4(b * N1 + i0, b * N1 + i1, b * N1 + i2, 0);
}

// ---------------------------------------------------------------------------
// Fused dual GEMM + BN + ReLU (+ interp for K2 part).
// Blocks [0, 128):   feats1 = relu(bn(A1 @ W1^T))            K=512 (NC=8)
// Blocks [128, 640): out    = relu(bn(A2 @ W2^T)) + interp3  K=256 (NC=4)
// CTA 128x256, 512 thr (16 warps 4x4), warp 32x64, K-chunk 64 (SW128).
// THREE-stage cp.async pipeline (2 chunks of prefetch slack).
// ---------------------------------------------------------------------------
#define STAGE 49152u
#define GEMM_DSMEM (3 * 49152 + 1024)

__device__ __forceinline__ void load_chunk(int tid, int bm, int K,
                                           uint32_t base, int c,
                                           const __half* __restrict__ A,
                                           const __half* __restrict__ B)
{
    uint32_t sb = base + (uint32_t)(c % 3) * STAGE;
    int kc = c << 6;
    for (int i = tid; i < 1024; i += 512) {
        int row = i >> 3, seg = i & 7;
        uint32_t off = SWZ((uint32_t)(row * 128 + seg * 16));
        CP16(sb + off, (const char*)(A + (size_t)(bm + row) * K + kc + seg * 8));
    }
    for (int i = tid; i < 2048; i += 512) {
        int row = i >> 3, seg = i & 7;
        uint32_t off = SWZ((uint32_t)(row * 128 + seg * 16));
        CP16(sb + 16384u + off, (const char*)(B + (size_t)row * K + kc + seg * 8));
    }
    CP_COMMIT();
}

__global__ __launch_bounds__(512, 1)
void gemm_fused_kernel(const __half* __restrict__ A1,
                       const __half* __restrict__ W1h,
                       const __half* __restrict__ A2,
                       const __half* __restrict__ W2h,
                       const float* __restrict__ b1, const float* __restrict__ g1,
                       const float* __restrict__ be1, const float* __restrict__ m1,
                       const float* __restrict__ v1,
                       const float* __restrict__ b2, const float* __restrict__ g2,
                       const float* __restrict__ be2, const float* __restrict__ m2,
                       const float* __restrict__ v2,
                       float* __restrict__ feats1,
                       float* __restrict__ out)
{
    extern __shared__ char dsm[];
    __shared__ float sScale[DO], sShift[DO], sBias[DO];

    const bool isK1 = (blockIdx.x < K1_BLOCKS);
    const __half* A  = isK1 ? A1 : A2;
    const __half* Bw = isK1 ? W1h : W2h;
    const float* bias  = isK1 ? b1 : b2;
    const float* gamma = isK1 ? g1 : g2;
    const float* beta  = isK1 ? be1 : be2;
    const float* mean  = isK1 ? m1 : m2;
    const float* var   = isK1 ? v1 : v2;
    float* C = isK1 ? feats1 : out;
    const int K  = isK1 ? D1 : D2;
    const int bm = (isK1 ? blockIdx.x : (blockIdx.x - K1_BLOCKS)) * 128;
    const int NC = K >> 6;

    const int tid  = threadIdx.x;
    const int wid  = tid >> 5;
    const int lane = tid & 31;
    const int wm   = wid >> 2;
    const int wn   = wid & 3;
    uint32_t base  = (smem_u32(dsm) + 1023u) & ~1023u;

    if (tid < DO) {
        float sc = gamma[tid] * rsqrtf(var[tid] + 1e-5f);
        sScale[tid] = sc;
        sShift[tid] = beta[tid] - mean[tid] * sc;
        sBias[tid]  = bias[tid];
    }

    float acc[2][8][4];
#pragma unroll
    for (int mi = 0; mi < 2; mi++)
#pragma unroll
        for (int ni = 0; ni < 8; ni++)
#pragma unroll
            for (int e = 0; e < 4; e++) acc[mi][ni][e] = 0.f;

    // 3-stage prologue: prefetch chunks 0 and 1
    load_chunk(tid, bm, K, base, 0, A, Bw);
    if (NC > 1) load_chunk(tid, bm, K, base, 1, A, Bw);

    const int arow  = wm * 32 + (lane & 15);
    const int acolb = (lane >> 4) * 16;
    const int g     = lane >> 3;
    const int bnrow = (g >> 1) * 8 + (lane & 7);
    const int bkb   = (g & 1) * 16;

    for (int c = 0; c < NC; c++) {
        if (c + 2 < NC) {
            load_chunk(tid, bm, K, base, c + 2, A, Bw);
            CP_WAIT2();
        } else if (c + 1 < NC) {
            CP_WAIT1();
        } else {
            CP_WAIT0();
        }
        __syncthreads();

        uint32_t sb = base + (uint32_t)(c % 3) * STAGE;
        uint32_t sA = sb, sB = sb + 16384u;

#pragma unroll
        for (int kk = 0; kk < 4; kk++) {
            uint32_t af[2][4], bf[8][2];
#pragma unroll
            for (int mi = 0; mi < 2; mi++) {
                uint32_t off = SWZ((uint32_t)((arow + mi * 16) * 128 + kk * 32 + acolb));
                ldsm4(af[mi], sA + off);
            }
#pragma unroll
            for (int p = 0; p < 4; p++) {
                uint32_t r[4];
                uint32_t off = SWZ((uint32_t)((wn * 64 + p * 16 + bnrow) * 128 + kk * 32 + bkb));
                ldsm4(r, sB + off);
                bf[2 * p + 0][0] = r[0]; bf[2 * p + 0][1] = r[1];
                bf[2 * p + 1][0] = r[2]; bf[2 * p + 1][1] = r[3];
            }
#pragma unroll
            for (int mi = 0; mi < 2; mi++)
#pragma unroll
                for (int ni = 0; ni < 8; ni++)
                    mma_f16(acc[mi][ni], af[mi], bf[ni]);
        }
        if (c + 1 < NC) __syncthreads();
    }

    const int tr = lane >> 2, tq = lane & 3;

    if (isK1) {
#pragma unroll
        for (int mi = 0; mi < 2; mi++) {
#pragma unroll
            for (int half = 0; half < 2; half++) {
                int row = bm + wm * 32 + mi * 16 + tr + half * 8;
                float* outRow = C + (size_t)row * DO;
#pragma unroll
                for (int ni = 0; ni < 8; ni++) {
                    int col = wn * 64 + ni * 8 + 2 * tq;
                    int e = half * 2;
                    float2 v;
                    v.x = fmaxf((acc[mi][ni][e + 0] + sBias[col])     * sScale[col]     + sShift[col],     0.f);
                    v.y = fmaxf((acc[mi][ni][e + 1] + sBias[col + 1]) * sScale[col + 1] + sShift[col + 1], 0.f);
                    *(float2*)(outRow + col) = v;
                }
            }
        }
        __threadfence();
        __syncthreads();
        if (tid == 0) atomicAdd(&g_k1done, 1);
    } else {
        if (tid == 0) {
            while (true) {
                int done;
                asm volatile("ld.global.acquire.gpu.b32 %0, [%1];"
                             : "=r"(done) : "l"(&g_k1done));
                if (done == K1_BLOCKS) break;
                __nanosleep(64);
            }
        }
        __syncthreads();
        __threadfence();

#pragma unroll
        for (int mi = 0; mi < 2; mi++) {
#pragma unroll
            for (int half = 0; half < 2; half++) {
                int row = bm + wm * 32 + mi * 16 + tr + half * 8;
                float4 w4  = g_knnw[row];
                int4   id4 = g_knni[row];
                const float* f0 = g_feats1 + (size_t)id4.x * DO;
                const float* f1 = g_feats1 + (size_t)id4.y * DO;
                const float* f2 = g_feats1 + (size_t)id4.z * DO;
                float* outRow = C + (size_t)row * DO;
#pragma unroll
                for (int ni = 0; ni < 8; ni++) {
                    int col = wn * 64 + ni * 8 + 2 * tq;
                    int e = half * 2;
                    float2 v;
                    v.x = fmaxf((acc[mi][ni][e + 0] + sBias[col])     * sScale[col]     + sShift[col],     0.f);
                    v.y = fmaxf((acc[mi][ni][e + 1] + sBias[col + 1]) * sScale[col + 1] + sShift[col + 1], 0.f);
                    float2 e0 = *(const float2*)(f0 + col);
                    float2 e1 = *(const float2*)(f1 + col);
                    float2 e2 = *(const float2*)(f2 + col);
                    v.x += w4.x * e0.x + w4.y * e1.x + w4.z * e2.x;
                    v.y += w4.x * e0.y + w4.y * e1.y + w4.z * e2.y;
                    *(float2*)(outRow + col) = v;
                }
            }
        }
    }
}

// ---------------------------------------------------------------------------
extern "C" void kernel_launch(void* const* d_in, const int* in_sizes, int n_in,
                              void* d_out, int out_size)
{
    const float* xyz1    = (const float*)d_in[0];
    const float* points1 = (const float*)d_in[1];
    const float* xyz2    = (const float*)d_in[2];
    const float* points2 = (const float*)d_in[3];
    const float* W1  = (const float*)d_in[4];
    const float* b1  = (const float*)d_in[5];
    const float* g1  = (const float*)d_in[6];
    const float* be1 = (const float*)d_in[7];
    const float* m1  = (const float*)d_in[8];
    const float* v1  = (const float*)d_in[9];
    const float* W2  = (const float*)d_in[10];
    const float* b2  = (const float*)d_in[11];
    const float* g2  = (const float*)d_in[12];
    const float* be2 = (const float*)d_in[13];
    const float* m2  = (const float*)d_in[14];
    const float* v2  = (const float*)d_in[15];
    float* out = (float*)d_out;

    float* feats1;
    __half *a1f, *a2f, *w1f, *w2f;
    cudaGetSymbolAddress((void**)&feats1, g_feats1);
    cudaGetSymbolAddress((void**)&a1f, gA1f);
    cudaGetSymbolAddress((void**)&a2f, gA2f);
    cudaGetSymbolAddress((void**)&w1f, gW1f);
    cudaGetSymbolAddress((void**)&w2f, gW2f);

    // Launch 1: 3-NN weights/indices + counter reset
    cudaFuncSetAttribute(knn_phase1_kernel,
                         cudaFuncAttributeMaxDynamicSharedMemorySize, KNN_SMEM);
    {
        dim3 grid(N2 / KNN_THREADS, BATCH);
        knn_phase1_kernel<<<grid, KNN_THREADS, KNN_SMEM>>>(xyz2, xyz1);
    }

    // Launch 2: convert points2 (largest)
    cvt_half_kernel<<<4096, 256>>>(points2, a2f, M2 * D2 / 4);
    // Launch 3: convert points1 + W1 + W2
    cvt_rest_kernel<<<2048, 256>>>(points1, a1f, W1, w1f, W2, w2f);

    cudaFuncSetAttribute(gemm_fused_kernel,
                         cudaFuncAttributeMaxDynamicSharedMemorySize, GEMM_DSMEM);

    // Launch 4 (ncu capture slot): fused K1 + K2(+interp), 640 CTAs.
    gemm_fused_kernel<<<K1_BLOCKS + K2_BLOCKS, 512, GEMM_DSMEM>>>(
        a1f, w1f, a2f, w2f,
        b1, g1, be1, m1, v1,
        b2, g2, be2, m2, v2,
        feats1, out);
}

// round 16
// speedup vs baseline: 1.0540x; 1.0353x over previous
#include <cuda_runtime.h>
#include <cuda_fp16.h>
#include <cstdint>
#include <math.h>

// Problem constants (fixed shapes from setup_inputs)
#define BATCH   4
#define N1      4096
#define N2      16384
#define D1      512
#define D2      256
#define DO      256
#define M1      (BATCH * N1)   // 16384
#define M2      (BATCH * N2)   // 65536
#define K1_BLOCKS (M1 / 128)   // 128
#define K2_BLOCKS (M2 / 128)   // 512
#define NSRC    (BATCH * N1)   // 16384 source rows

// ---------------------------------------------------------------------------
// Device scratch (allocation-free rule: __device__ globals)
// ---------------------------------------------------------------------------
__device__ float g_feats1[M1 * DO];                         // 16 MB
__device__ __align__(16) __half gA1f[M1 * D1];              // 16 MB
__device__ __align__(16) __half gA2f[M2 * D2];              // 32 MB
__device__ __align__(16) __half gW1f[DO * D1];
__device__ __align__(16) __half gW2f[DO * D2];
__device__ float4 g_knnw[M2];                               // weights (w0,w1,w2,-)
__device__ int4   g_knni[M2];                               // global feats1 row idx
__device__ int    g_k1done;                                 // K1 CTA completion count
__device__ __align__(16) __half gKA[M2 * 16];               // target MMA rows (2 MB)
__device__ __align__(16) __half gKB[NSRC * 16];             // source MMA rows (512 KB)

// ---------------------------------------------------------------------------
// Helpers
// ---------------------------------------------------------------------------
__device__ __forceinline__ uint32_t smem_u32(const void* p) {
    uint32_t a;
    asm("{ .reg .u64 t; cvta.to.shared.u64 t, %1; cvt.u32.u64 %0, t; }"
        : "=r"(a) : "l"(p));
    return a;
}

#define SWZ(o) ((o) ^ (((o) >> 3) & 0x70))

#define CP16(dst, src) \
    asm volatile("cp.async.cg.shared.global [%0], [%1], 16;" :: "r"(dst), "l"(src) : "memory")
#define CP_COMMIT() asm volatile("cp.async.commit_group;" ::: "memory")
#define CP_WAIT0()  asm volatile("cp.async.wait_group 0;" ::: "memory")
#define CP_WAIT1()  asm volatile("cp.async.wait_group 1;" ::: "memory")
#define CP_WAIT2()  asm volatile("cp.async.wait_group 2;" ::: "memory")

__device__ __forceinline__ void ldsm4(uint32_t r[4], uint32_t addr) {
    asm volatile("ldmatrix.sync.aligned.m8n8.x4.shared.b16 {%0,%1,%2,%3}, [%4];"
        : "=r"(r[0]), "=r"(r[1]), "=r"(r[2]), "=r"(r[3]) : "r"(addr));
}
__device__ __forceinline__ void mma_f16(float d[4], const uint32_t a[4], const uint32_t b[2]) {
    asm volatile("mma.sync.aligned.m16n8k16.row.col.f32.f16.f16.f32 "
        "{%0,%1,%2,%3}, {%4,%5,%6,%7}, {%8,%9}, {%0,%1,%2,%3};"
        : "+f"(d[0]), "+f"(d[1]), "+f"(d[2]), "+f"(d[3])
        : "r"(a[0]), "r"(a[1]), "r"(a[2]), "r"(a[3]), "r"(b[0]), "r"(b[1]));
}
// MMA with zero C, fresh D
__device__ __forceinline__ void mma_f16_z(float d[4], const uint32_t a[4], const uint32_t b[2]) {
    float z = 0.f;
    asm volatile("mma.sync.aligned.m16n8k16.row.col.f32.f16.f16.f32 "
        "{%0,%1,%2,%3}, {%4,%5,%6,%7}, {%8,%9}, {%10,%10,%10,%10};"
        : "=f"(d[0]), "=f"(d[1]), "=f"(d[2]), "=f"(d[3])
        : "r"(a[0]), "r"(a[1]), "r"(a[2]), "r"(a[3]), "r"(b[0]), "r"(b[1]), "f"(z));
}

// ---------------------------------------------------------------------------
// fp32 -> fp16 converts
// ---------------------------------------------------------------------------
__global__ __launch_bounds__(256)
void cvt_half_kernel(const float* __restrict__ x, __half* __restrict__ y, int n4)
{
    int i = blockIdx.x * blockDim.x + threadIdx.x;
    int stride = gridDim.x * blockDim.x;
    for (; i < n4; i += stride) {
        float4 v = ((const float4*)x)[i];
        ((__half2*)y)[2 * i + 0] = __floats2half2_rn(v.x, v.y);
        ((__half2*)y)[2 * i + 1] = __floats2half2_rn(v.z, v.w);
    }
}

#define CVT1_N4 (M1 * D1 / 4)
#define CVTW1_N4 (DO * D1 / 4)
#define CVTW2_N4 (DO * D2 / 4)

__global__ __launch_bounds__(256)
void cvt_rest_kernel(const float* __restrict__ x1, __half* __restrict__ y1,
                     const float* __restrict__ x2, __half* __restrict__ y2,
                     const float* __restrict__ x3, __half* __restrict__ y3)
{
    int i = blockIdx.x * blockDim.x + threadIdx.x;
    int stride = gridDim.x * blockDim.x;
    int total = CVT1_N4 + CVTW1_N4 + CVTW2_N4;
    for (; i < total; i += stride) {
        const float* x; __half* y; int j;
        if (i < CVT1_N4)                { x = x1; y = y1; j = i; }
        else if (i < CVT1_N4 + CVTW1_N4){ x = x2; y = y2; j = i - CVT1_N4; }
        else                            { x = x3; y = y3; j = i - CVT1_N4 - CVTW1_N4; }
        float4 v = ((const float4*)x)[j];
        ((__half2*)y)[2 * j + 0] = __floats2half2_rn(v.x, v.y);
        ((__half2*)y)[2 * j + 1] = __floats2half2_rn(v.z, v.w);
    }
}

// ---------------------------------------------------------------------------
// KNN prep: build split-fp16 MMA rows.
// Target row (A): [th0,th1,th2, tl0,tl1,tl2, th0,th1,th2, 1, 1, 0...]
// Source row (B): [ph0,ph1,ph2, ph0,ph1,ph2, pl0,pl1,pl2, snh, snl, 0...]
//   p = -2*s, snorm = |s|^2 split hi/lo.
// A.B over k16 = -2 t.s + |s|^2 (hi*hi + lo*hi + hi*lo + snorm), err ~1e-6.
// ---------------------------------------------------------------------------
__global__ __launch_bounds__(256)
void knn_prep_kernel(const float* __restrict__ xyz2,
                     const float* __restrict__ xyz1)
{
    int i = blockIdx.x * blockDim.x + threadIdx.x;
    if (i < M2) {
        const float* p = xyz2 + (size_t)i * 3;
        float x = p[0], y = p[1], z = p[2];
        __half hx = __float2half_rn(x), hy = __float2half_rn(y), hz = __float2half_rn(z);
        __half lx = __float2half_rn(x - __half2float(hx));
        __half ly = __float2half_rn(y - __half2float(hy));
        __half lz = __float2half_rn(z - __half2float(hz));
        __align__(16) __half r[16];
        r[0]=hx; r[1]=hy; r[2]=hz; r[3]=lx; r[4]=ly; r[5]=lz;
        r[6]=hx; r[7]=hy; r[8]=hz;
        r[9]=__float2half_rn(1.f); r[10]=__float2half_rn(1.f);
        r[11]=__half(0.f); r[12]=__half(0.f); r[13]=__half(0.f); r[14]=__half(0.f); r[15]=__half(0.f);
        uint4* d = (uint4*)(gKA + (size_t)i * 16);
        d[0] = ((uint4*)r)[0]; d[1] = ((uint4*)r)[1];
    } else if (i < M2 + NSRC) {
        int j = i - M2;
        const float* p = xyz1 + (size_t)j * 3;
        float x = p[0], y = p[1], z = p[2];
        float px = -2.f * x, py = -2.f * y, pz = -2.f * z;
        __half hx = __float2half_rn(px), hy = __float2half_rn(py), hz = __float2half_rn(pz);
        __half lx = __float2half_rn(px - __half2float(hx));
        __half ly = __float2half_rn(py - __half2float(hy));
        __half lz = __float2half_rn(pz - __half2float(hz));
        float sn = fmaf(x, x, fmaf(y, y, z * z));
        __half snh = __float2half_rn(sn);
        __half snl = __float2half_rn(sn - __half2float(snh));
        __align__(16) __half r[16];
        r[0]=hx; r[1]=hy; r[2]=hz; r[3]=hx; r[4]=hy; r[5]=hz;
        r[6]=lx; r[7]=ly; r[8]=lz; r[9]=snh; r[10]=snl;
        r[11]=__half(0.f); r[12]=__half(0.f); r[13]=__half(0.f); r[14]=__half(0.f); r[15]=__half(0.f);
        uint4* d = (uint4*)(gKB + (size_t)j * 16);
        d[0] = ((uint4*)r)[0]; d[1] = ((uint4*)r)[1];
    }
}

// ---------------------------------------------------------------------------
// KNN via tensor cores. CTA: 128 targets (8 warps x m16) x all 4096 sources,
// 512-source double-buffered smem chunks. Per-thread top-3, quad-shuffle merge.
// ---------------------------------------------------------------------------
#define KCH   512                 // sources per chunk
#define KROW  48u                 // smem row stride (32B data + 16B pad)
#define KNN_SA (128 * 48)         // 6144
#define KNN_SB (KCH * 48)         // 24576
#define KNN_MMA_SMEM (KNN_SA + 2 * KNN_SB + 128)

#define INS3(K0,K1,K2,I0,I1,I2,v,c) \
    if ((v) < K2) { \
        if ((v) < K0)      { K2=K1; I2=I1; K1=K0; I1=I0; K0=(v); I0=(c); } \
        else if ((v) < K1) { K2=K1; I2=I1; K1=(v); I1=(c); } \
        else               { K2=(v); I2=(c); } }

__global__ __launch_bounds__(256)
void knn_mma_kernel(const float* __restrict__ xyz2)
{
    extern __shared__ char dsm[];
    const int tid  = threadIdx.x;
    const int wid  = tid >> 5;
    const int lane = tid & 31;
    const int b    = blockIdx.y;
    const int bm   = blockIdx.x * 128;           // target base within batch

    if (blockIdx.x == 0 && b == 0 && tid == 0) g_k1done = 0;

    uint32_t base = (smem_u32(dsm) + 127u) & ~127u;
    uint32_t sA = base;
    uint32_t sB = base + KNN_SA;

    const __half* gA = gKA + ((size_t)b * N2 + bm) * 16;
    const __half* gB = gKB + ((size_t)b * N1) * 16;

    // chunk loader: 512 rows x 32B -> stride-48 rows; 1024 cp16 / 256 thr
    auto loadB = [&](int c) {
        uint32_t dst = sB + (uint32_t)(c & 1) * KNN_SB;
        const __half* src = gB + (size_t)c * KCH * 16;
        for (int i = tid; i < 1024; i += 256) {
            int row = i >> 1, h = i & 1;
            CP16(dst + row * KROW + h * 16u, (const char*)(src + row * 16 + h * 8));
        }
        CP_COMMIT();
    };

    // prologue: A rows (128 rows x 2 halves = 256 cp16 = exactly 1 per thread)
    {
        int row = tid >> 1, h = tid & 1;
        CP16(sA + row * KROW + h * 16u, (const char*)(gA + row * 16 + h * 8));
    }
    loadB(0);   // commit covers A + B0

    float K0l = 3.4e38f, K1l = 3.4e38f, K2l = 3.4e38f;
    float K0h = 3.4e38f, K1h = 3.4e38f, K2h = 3.4e38f;
    int I0l = 0, I1l = 0, I2l = 0, I0h = 0, I1h = 0, I2h = 0;

    const int tr  = lane >> 2, tq = lane & 3;
    const int g   = lane >> 3;
    const int bnrow = (g >> 1) * 8 + (lane & 7);
    const uint32_t bkb = (g & 1) * 16u;

    uint32_t af[4];
    const int NCH = N1 / KCH;   // 8

    for (int c = 0; c < NCH; c++) {
        if (c + 1 < NCH) { loadB(c + 1); CP_WAIT1(); }
        else             { CP_WAIT0(); }
        __syncthreads();
        if (c == 0) {
            ldsm4(af, sA + (uint32_t)(wid * 16 + (lane & 15)) * KROW + (uint32_t)(lane >> 4) * 16u);
        }
        uint32_t sBc = sB + (uint32_t)(c & 1) * KNN_SB;

        for (int blk = 0; blk < 8; blk++) {       // 64 sources per blk
            uint32_t bf[8][2];
#pragma unroll
            for (int p = 0; p < 4; p++) {
                uint32_t r[4];
                ldsm4(r, sBc + (uint32_t)(blk * 64 + p * 16 + bnrow) * KROW + bkb);
                bf[2 * p + 0][0] = r[0]; bf[2 * p + 0][1] = r[1];
                bf[2 * p + 1][0] = r[2]; bf[2 * p + 1][1] = r[3];
            }
            float d[8][4];
#pragma unroll
            for (int ni = 0; ni < 8; ni++)
                mma_f16_z(d[ni], af, bf[ni]);

            int colbase = c * KCH + blk * 64 + 2 * tq;
#pragma unroll
            for (int ni = 0; ni < 8; ni++) {
                int cb = colbase + ni * 8;
                float v0 = d[ni][0], v1 = d[ni][1], v2 = d[ni][2], v3 = d[ni][3];
                INS3(K0l, K1l, K2l, I0l, I1l, I2l, v0, cb);
                INS3(K0l, K1l, K2l, I0l, I1l, I2l, v1, cb + 1);
                INS3(K0h, K1h, K2h, I0h, I1h, I2h, v2, cb);
                INS3(K0h, K1h, K2h, I0h, I1h, I2h, v3, cb + 1);
            }
        }
        if (c + 1 < NCH) __syncthreads();
    }

    // merge top-3 across the 4 quad threads (butterfly: all lanes converge)
#pragma unroll
    for (int off = 1; off <= 2; off <<= 1) {
        float m0 = __shfl_xor_sync(0xFFFFFFFFu, K0l, off);
        float m1 = __shfl_xor_sync(0xFFFFFFFFu, K1l, off);
        float m2 = __shfl_xor_sync(0xFFFFFFFFu, K2l, off);
        int   j0 = __shfl_xor_sync(0xFFFFFFFFu, I0l, off);
        int   j1 = __shfl_xor_sync(0xFFFFFFFFu, I1l, off);
        int   j2 = __shfl_xor_sync(0xFFFFFFFFu, I2l, off);
        INS3(K0l, K1l, K2l, I0l, I1l, I2l, m0, j0);
        INS3(K0l, K1l, K2l, I0l, I1l, I2l, m1, j1);
        INS3(K0l, K1l, K2l, I0l, I1l, I2l, m2, j2);
        m0 = __shfl_xor_sync(0xFFFFFFFFu, K0h, off);
        m1 = __shfl_xor_sync(0xFFFFFFFFu, K1h, off);
        m2 = __shfl_xor_sync(0xFFFFFFFFu, K2h, off);
        j0 = __shfl_xor_sync(0xFFFFFFFFu, I0h, off);
        j1 = __shfl_xor_sync(0xFFFFFFFFu, I1h, off);
        j2 = __shfl_xor_sync(0xFFFFFFFFu, I2h, off);
        INS3(K0h, K1h, K2h, I0h, I1h, I2h, m0, j0);
        INS3(K0h, K1h, K2h, I0h, I1h, I2h, m1, j1);
        INS3(K0h, K1h, K2h, I0h, I1h, I2h, m2, j2);
    }

    if (tq == 0) {
#pragma unroll
        for (int half = 0; half < 2; half++) {
            int r = bm + wid * 16 + tr + half * 8;
            float kk0 = half ? K0h : K0l, kk1 = half ? K1h : K1l, kk2 = half ? K2h : K2l;
            int   ii0 = half ? I0h : I0l, ii1 = half ? I1h : I1l, ii2 = half ? I2h : I2l;
            const float* tp = xyz2 + ((size_t)b * N2 + r) * 3;
            float tx = tp[0], ty = tp[1], tz = tp[2];
            float tt = fmaf(tx, tx, fmaf(ty, ty, tz * tz));
            float w0 = 1.f / (kk0 + tt + 1e-8f);
            float w1 = 1.f / (kk1 + tt + 1e-8f);
            float w2 = 1.f / (kk2 + tt + 1e-8f);
            float inv = 1.f / (w0 + w1 + w2);
            int gidx = b * N2 + r;
            g_knnw[gidx] = make_float4(w0 * inv, w1 * inv, w2 * inv, 0.f);
            g_knni[gidx] = make_int4(b * N1 + ii0, b * N1 + ii1, b * N1 + ii2, 0);
        }
    }
}

// ---------------------------------------------------------------------------
// Fused dual GEMM + BN + ReLU (+ interp for K2 part).  (unchanged from R13)
// ---------------------------------------------------------------------------
#define STAGE 49152u
#define GEMM_DSMEM (3 * 49152 + 1024)

__device__ __forceinline__ void load_chunk(int tid, int bm, int K,
                                           uint32_t base, int c,
                                           const __half* __restrict__ A,
                                           const __half* __restrict__ B)
{
    uint32_t sb = base + (uint32_t)(c % 3) * STAGE;
    int kc = c << 6;
    for (int i = tid; i < 1024; i += 512) {
        int row = i >> 3, seg = i & 7;
        uint32_t off = SWZ((uint32_t)(row * 128 + seg * 16));
        CP16(sb + off, (const char*)(A + (size_t)(bm + row) * K + kc + seg * 8));
    }
    for (int i = tid; i < 2048; i += 512) {
        int row = i >> 3, seg = i & 7;
        uint32_t off = SWZ((uint32_t)(row * 128 + seg * 16));
        CP16(sb + 16384u + off, (const char*)(B + (size_t)row * K + kc + seg * 8));
    }
    CP_COMMIT();
}

__global__ __launch_bounds__(512, 1)
void gemm_fused_kernel(const __half* __restrict__ A1,
                       const __half* __restrict__ W1h,
                       const __half* __restrict__ A2,
                       const __half* __restrict__ W2h,
                       const float* __restrict__ b1, const float* __restrict__ g1,
                       const float* __restrict__ be1, const float* __restrict__ m1,
                       const float* __restrict__ v1,
                       const float* __restrict__ b2, const float* __restrict__ g2,
                       const float* __restrict__ be2, const float* __restrict__ m2,
                       const float* __restrict__ v2,
                       float* __restrict__ feats1,
                       float* __restrict__ out)
{
    extern __shared__ char dsm[];
    __shared__ float sScale[DO], sShift[DO], sBias[DO];

    const bool isK1 = (blockIdx.x < K1_BLOCKS);
    const __half* A  = isK1 ? A1 : A2;
    const __half* Bw = isK1 ? W1h : W2h;
    const float* bias  = isK1 ? b1 : b2;
    const float* gamma = isK1 ? g1 : g2;
    const float* beta  = isK1 ? be1 : be2;
    const float* mean  = isK1 ? m1 : m2;
    const float* var   = isK1 ? v1 : v2;
    float* C = isK1 ? feats1 : out;
    const int K  = isK1 ? D1 : D2;
    const int bm = (isK1 ? blockIdx.x : (blockIdx.x - K1_BLOCKS)) * 128;
    const int NC = K >> 6;

    const int tid  = threadIdx.x;
    const int wid  = tid >> 5;
    const int lane = tid & 31;
    const int wm   = wid >> 2;
    const int wn   = wid & 3;
    uint32_t base  = (smem_u32(dsm) + 1023u) & ~1023u;

    if (tid < DO) {
        float sc = gamma[tid] * rsqrtf(var[tid] + 1e-5f);
        sScale[tid] = sc;
        sShift[tid] = beta[tid] - mean[tid] * sc;
        sBias[tid]  = bias[tid];
    }

    float acc[2][8][4];
#pragma unroll
    for (int mi = 0; mi < 2; mi++)
#pragma unroll
        for (int ni = 0; ni < 8; ni++)
#pragma unroll
            for (int e = 0; e < 4; e++) acc[mi][ni][e] = 0.f;

    load_chunk(tid, bm, K, base, 0, A, Bw);
    if (NC > 1) load_chunk(tid, bm, K, base, 1, A, Bw);

    const int arow  = wm * 32 + (lane & 15);
    const int acolb = (lane >> 4) * 16;
    const int g     = lane >> 3;
    const int bnrow = (g >> 1) * 8 + (lane & 7);
    const int bkb   = (g & 1) * 16;

    for (int c = 0; c < NC; c++) {
        if (c + 2 < NC) {
            load_chunk(tid, bm, K, base, c + 2, A, Bw);
            CP_WAIT2();
        } else if (c + 1 < NC) {
            CP_WAIT1();
        } else {
            CP_WAIT0();
        }
        __syncthreads();

        uint32_t sb = base + (uint32_t)(c % 3) * STAGE;
        uint32_t sA = sb, sB = sb + 16384u;

#pragma unroll
        for (int kk = 0; kk < 4; kk++) {
            uint32_t af[2][4], bf[8][2];
#pragma unroll
            for (int mi = 0; mi < 2; mi++) {
                uint32_t off = SWZ((uint32_t)((arow + mi * 16) * 128 + kk * 32 + acolb));
                ldsm4(af[mi], sA + off);
            }
#pragma unroll
            for (int p = 0; p < 4; p++) {
                uint32_t r[4];
                uint32_t off = SWZ((uint32_t)((wn * 64 + p * 16 + bnrow) * 128 + kk * 32 + bkb));
                ldsm4(r, sB + off);
                bf[2 * p + 0][0] = r[0]; bf[2 * p + 0][1] = r[1];
                bf[2 * p + 1][0] = r[2]; bf[2 * p + 1][1] = r[3];
            }
#pragma unroll
            for (int mi = 0; mi < 2; mi++)
#pragma unroll
                for (int ni = 0; ni < 8; ni++)
                    mma_f16(acc[mi][ni], af[mi], bf[ni]);
        }
        if (c + 1 < NC) __syncthreads();
    }

    const int tr = lane >> 2, tq = lane & 3;

    if (isK1) {
#pragma unroll
        for (int mi = 0; mi < 2; mi++) {
#pragma unroll
            for (int half = 0; half < 2; half++) {
                int row = bm + wm * 32 + mi * 16 + tr + half * 8;
                float* outRow = C + (size_t)row * DO;
#pragma unroll
                for (int ni = 0; ni < 8; ni++) {
                    int col = wn * 64 + ni * 8 + 2 * tq;
                    int e = half * 2;
                    float2 v;
                    v.x = fmaxf((acc[mi][ni][e + 0] + sBias[col])     * sScale[col]     + sShift[col],     0.f);
                    v.y = fmaxf((acc[mi][ni][e + 1] + sBias[col + 1]) * sScale[col + 1] + sShift[col + 1], 0.f);
                    *(float2*)(outRow + col) = v;
                }
            }
        }
        __threadfence();
        __syncthreads();
        if (tid == 0) atomicAdd(&g_k1done, 1);
    } else {
        if (tid == 0) {
            while (true) {
                int done;
                asm volatile("ld.global.acquire.gpu.b32 %0, [%1];"
                             : "=r"(done) : "l"(&g_k1done));
                if (done == K1_BLOCKS) break;
                __nanosleep(64);
            }
        }
        __syncthreads();
        __threadfence();

#pragma unroll
        for (int mi = 0; mi < 2; mi++) {
#pragma unroll
            for (int half = 0; half < 2; half++) {
                int row = bm + wm * 32 + mi * 16 + tr + half * 8;
                float4 w4  = g_knnw[row];
                int4   id4 = g_knni[row];
                const float* f0 = g_feats1 + (size_t)id4.x * DO;
                const float* f1 = g_feats1 + (size_t)id4.y * DO;
                const float* f2 = g_feats1 + (size_t)id4.z * DO;
                float* outRow = C + (size_t)row * DO;
#pragma unroll
                for (int ni = 0; ni < 8; ni++) {
                    int col = wn * 64 + ni * 8 + 2 * tq;
                    int e = half * 2;
                    float2 v;
                    v.x = fmaxf((acc[mi][ni][e + 0] + sBias[col])     * sScale[col]     + sShift[col],     0.f);
                    v.y = fmaxf((acc[mi][ni][e + 1] + sBias[col + 1]) * sScale[col + 1] + sShift[col + 1], 0.f);
                    float2 e0 = *(const float2*)(f0 + col);
                    float2 e1 = *(const float2*)(f1 + col);
                    float2 e2 = *(const float2*)(f2 + col);
                    v.x += w4.x * e0.x + w4.y * e1.x + w4.z * e2.x;
                    v.y += w4.x * e0.y + w4.y * e1.y + w4.z * e2.y;
                    *(float2*)(outRow + col) = v;
                }
            }
        }
    }
}

// ---------------------------------------------------------------------------
extern "C" void kernel_launch(void* const* d_in, const int* in_sizes, int n_in,
                              void* d_out, int out_size)
{
    const float* xyz1    = (const float*)d_in[0];
    const float* points1 = (const float*)d_in[1];
    const float* xyz2    = (const float*)d_in[2];
    const float* points2 = (const float*)d_in[3];
    const float* W1  = (const float*)d_in[4];
    const float* b1  = (const float*)d_in[5];
    const float* g1  = (const float*)d_in[6];
    const float* be1 = (const float*)d_in[7];
    const float* m1  = (const float*)d_in[8];
    const float* v1  = (const float*)d_in[9];
    const float* W2  = (const float*)d_in[10];
    const float* b2  = (const float*)d_in[11];
    const float* g2  = (const float*)d_in[12];
    const float* be2 = (const float*)d_in[13];
    const float* m2  = (const float*)d_in[14];
    const float* v2  = (const float*)d_in[15];
    float* out = (float*)d_out;

    float* feats1;
    __half *a1f, *a2f, *w1f, *w2f;
    cudaGetSymbolAddress((void**)&feats1, g_feats1);
    cudaGetSymbolAddress((void**)&a1f, gA1f);
    cudaGetSymbolAddress((void**)&a2f, gA2f);
    cudaGetSymbolAddress((void**)&w1f, gW1f);
    cudaGetSymbolAddress((void**)&w2f, gW2f);

    // Launch 1: convert points2 (largest)
    cvt_half_kernel<<<4096, 256>>>(points2, a2f, M2 * D2 / 4);
    // Launch 2: convert points1 + W1 + W2
    cvt_rest_kernel<<<2048, 256>>>(points1, a1f, W1, w1f, W2, w2f);
    // Launch 3: KNN prep (split-fp16 MMA row encodings)
    knn_prep_kernel<<<(M2 + NSRC + 255) / 256, 256>>>(xyz2, xyz1);

    // Launch 4 (ncu capture slot): tensor-core 3-NN
    cudaFuncSetAttribute(knn_mma_kernel,
                         cudaFuncAttributeMaxDynamicSharedMemorySize, KNN_MMA_SMEM);
    {
        dim3 grid(N2 / 128, BATCH);
        knn_mma_kernel<<<grid, 256, KNN_MMA_SMEM>>>(xyz2);
    }

    cudaFuncSetAttribute(gemm_fused_kernel,
                         cudaFuncAttributeMaxDynamicSharedMemorySize, GEMM_DSMEM);

    // Launch 5: fused K1 + K2(+interp), 640 CTAs.
    gemm_fused_kernel<<<K1_BLOCKS + K2_BLOCKS, 512, GEMM_DSMEM>>>(
        a1f, w1f, a2f, w2f,
        b1, g1, be1, m1, v1,
        b2, g2, be2, m2, v2,
        feats1, out);
}